// round 12
// baseline (speedup 1.0000x reference)
#include <cuda_runtime.h>
#include <cuda_bf16.h>
#include <cuda_fp16.h>
#include <cstdint>

// ---------------------------------------------------------------------------
constexpr int B_ = 2048, Z_ = 128, H_ = 1024, O_ = 3072, E_ = 8;
constexpr int MAXT = B_ / 128 + E_;   // 24
constexpr int BM = 128, BN = 128, BK = 32;
constexpr int NSTG = 3;

// GEMM1 (bf16 3-term) stage layout: A hi/lo 128x32 (80B-stride), B hi/lo 32x128
constexpr int OFF_AH = 0;
constexpr int OFF_AL = 10240;
constexpr int OFF_BH = 20480;
constexpr int OFF_BL = 28672;
constexpr int STAGE  = 36864;
constexpr int OFF_BIAS = NSTG * STAGE;       // 110592
constexpr int OFF_PERM = OFF_BIAS + 512;
constexpr int SMEM_TOTAL = OFF_PERM + 512;   // 111616

// GEMM2 (fp16 single-term, BN2=64): A 128x32 fp16 (80B rows), B 32x64 fp16 (128B rows)
constexpr int BN2 = 64;
constexpr int F2_A  = 0;
constexpr int F2_B  = 10240;
constexpr int F2_STAGE = 14336;
constexpr int F2_BIAS = NSTG * F2_STAGE;     // 43008 (64 floats)
constexpr int F2_PERM = F2_BIAS + 256;       // 43264 (128 ints)
constexpr int SMEM2_TOTAL = F2_PERM + 512;   // 43776

constexpr int G1_BLOCKS = (H_ / BN) * MAXT;  // 192
constexpr int CONVB    = 2048;               // W2 convert blocks
constexpr int W1_BLOCKS = E_ * Z_ * H_ / 4 / 256;   // 1024

// ---------------------------------------------------------------------------
__device__ int g_idx[B_], g_offsets[E_ + 1], g_perm[B_];
__device__ int g_tile_e[MAXT], g_tile_r[MAXT], g_num_tiles;

__device__ __align__(16) __nv_bfloat16 g_zg_h[(B_ + 128) * Z_];
__device__ __align__(16) __nv_bfloat16 g_zg_l[(B_ + 128) * Z_];
__device__ __align__(16) __half       g_hg[(B_ + 128) * H_];
__device__ __align__(16) __nv_bfloat16 g_w1_h[E_ * Z_ * H_];
__device__ __align__(16) __nv_bfloat16 g_w1_l[E_ * Z_ * H_];
__device__ __align__(16) __half       g_w2f[(size_t)E_ * H_ * O_];

// ---------------------------------------------------------------------------
// PTX helpers (arch-agnostic, sm_80+)
// ---------------------------------------------------------------------------
__device__ __forceinline__ uint32_t smem_u32(const void* p) {
    return (uint32_t)__cvta_generic_to_shared(p);
}
__device__ __forceinline__ void cp16(uint32_t dst, const void* src) {
    asm volatile("cp.async.cg.shared.global [%0], [%1], 16;" :: "r"(dst), "l"(src) : "memory");
}
__device__ __forceinline__ void cp_commit() {
    asm volatile("cp.async.commit_group;" ::: "memory");
}
__device__ __forceinline__ void cp_wait2() {
    asm volatile("cp.async.wait_group 2;" ::: "memory");
}
__device__ __forceinline__ void ldsm4(uint32_t* r, uint32_t a) {
    asm volatile("ldmatrix.sync.aligned.m8n8.x4.shared.b16 {%0,%1,%2,%3}, [%4];"
                 : "=r"(r[0]), "=r"(r[1]), "=r"(r[2]), "=r"(r[3]) : "r"(a));
}
__device__ __forceinline__ void ldsm4t(uint32_t* r, uint32_t a) {
    asm volatile("ldmatrix.sync.aligned.m8n8.x4.trans.shared.b16 {%0,%1,%2,%3}, [%4];"
                 : "=r"(r[0]), "=r"(r[1]), "=r"(r[2]), "=r"(r[3]) : "r"(a));
}
__device__ __forceinline__ void mma_bf16(float* d, const uint32_t* a, uint32_t b0, uint32_t b1) {
    asm volatile(
        "mma.sync.aligned.m16n8k16.row.col.f32.bf16.bf16.f32 "
        "{%0,%1,%2,%3}, {%4,%5,%6,%7}, {%8,%9}, {%0,%1,%2,%3};"
        : "+f"(d[0]), "+f"(d[1]), "+f"(d[2]), "+f"(d[3])
        : "r"(a[0]), "r"(a[1]), "r"(a[2]), "r"(a[3]), "r"(b0), "r"(b1));
}
__device__ __forceinline__ void mma_f16(float* d, const uint32_t* a, uint32_t b0, uint32_t b1) {
    asm volatile(
        "mma.sync.aligned.m16n8k16.row.col.f32.f16.f16.f32 "
        "{%0,%1,%2,%3}, {%4,%5,%6,%7}, {%8,%9}, {%0,%1,%2,%3};"
        : "+f"(d[0]), "+f"(d[1]), "+f"(d[2]), "+f"(d[3])
        : "r"(a[0]), "r"(a[1]), "r"(a[2]), "r"(a[3]), "r"(b0), "r"(b1));
}

__device__ __forceinline__ void split4(float4 v, __nv_bfloat162* dh,
                                       __nv_bfloat162* dl, int i) {
    __nv_bfloat16 h0 = __float2bfloat16(v.x), h1 = __float2bfloat16(v.y);
    __nv_bfloat16 h2 = __float2bfloat16(v.z), h3 = __float2bfloat16(v.w);
    __nv_bfloat16 l0 = __float2bfloat16(v.x - __bfloat162float(h0));
    __nv_bfloat16 l1 = __float2bfloat16(v.y - __bfloat162float(h1));
    __nv_bfloat16 l2 = __float2bfloat16(v.z - __bfloat162float(h2));
    __nv_bfloat16 l3 = __float2bfloat16(v.w - __bfloat162float(h3));
    dh[2 * i]     = __nv_bfloat162(h0, h1);
    dh[2 * i + 1] = __nv_bfloat162(h2, h3);
    dl[2 * i]     = __nv_bfloat162(l0, l1);
    dl[2 * i + 1] = __nv_bfloat162(l2, l3);
}

__device__ __forceinline__ void cvt_f16_store8(__half2* dst, int i, float4 v) {
    __half2 a = __halves2half2(__float2half_rn(v.x), __float2half_rn(v.y));
    __half2 b = __halves2half2(__float2half_rn(v.z), __float2half_rn(v.w));
    uint2 u;
    u.x = *(uint32_t*)&a;
    u.y = *(uint32_t*)&b;
    *(uint2*)(dst + 2 * i) = u;
}

// ---------------------------------------------------------------------------
// route (blocks 0..7) fused with W1 split (blocks 8..) — main stream.
// Routing is bit-exact vs JAX (exact small integers in fp32).
// ---------------------------------------------------------------------------
__global__ void route_w1(const float* __restrict__ z, const float4* __restrict__ W1) {
    int bid = blockIdx.x, t = threadIdx.x;
    if (bid < 8) {
        int i = bid * 256 + t;
        const float* zr = z + (size_t)i * Z_;
        float s = 0.0f;
        #pragma unroll 8
        for (int k = 0; k < Z_; k++)
            s += floorf(fabsf(zr[k]) * 1000.0f);
        g_idx[i] = ((int)s) & (E_ - 1);
    } else {
        int i = (bid - 8) * 256 + t;   // < 262144
        split4(W1[i], (__nv_bfloat162*)g_w1_h, (__nv_bfloat162*)g_w1_l, i);
    }
}

// W2 fp32 -> fp16 convert; side stream, full occupancy.
__global__ void w2conv(const float4* __restrict__ W2) {
    const int stride = CONVB * 256;
    __half2* dst = (__half2*)g_w2f;
    int base = blockIdx.x * 256 + threadIdx.x;
    #pragma unroll
    for (int o = 0; o < 3; o++) {
        int i0 = base + (o * 4) * stride;
        float4 v0 = W2[i0];
        float4 v1 = W2[i0 + stride];
        float4 v2 = W2[i0 + 2 * stride];
        float4 v3 = W2[i0 + 3 * stride];
        cvt_f16_store8(dst, i0,              v0);
        cvt_f16_store8(dst, i0 + stride,     v1);
        cvt_f16_store8(dst, i0 + 2 * stride, v2);
        cvt_f16_store8(dst, i0 + 3 * stride, v3);
    }
}

__global__ void scan_scatter() {
    __shared__ int cnt[E_], cur[E_], offs[E_];
    int t = threadIdx.x;
    if (t < E_) { cnt[t] = 0; cur[t] = 0; }
    __syncthreads();
    for (int i = t; i < B_; i += blockDim.x) atomicAdd(&cnt[g_idx[i]], 1);
    __syncthreads();
    if (t == 0) {
        int o = 0, nt = 0;
        g_offsets[0] = 0;
        for (int e = 0; e < E_; e++) {
            int c = cnt[e];
            offs[e] = o;
            for (int r = 0; r < c; r += BM) { g_tile_e[nt] = e; g_tile_r[nt] = r; nt++; }
            o += c;
            g_offsets[e + 1] = o;
        }
        g_num_tiles = nt;
    }
    __syncthreads();
    for (int i = t; i < B_; i += blockDim.x) {
        int e = g_idx[i];
        int pos = offs[e] + atomicAdd(&cur[e], 1);
        g_perm[pos] = i;
    }
}

// z gather + bf16 hi/lo split (perm-dependent)
__global__ void prep_z(const float4* __restrict__ z4) {
    int idx = blockIdx.x * 256 + threadIdx.x;    // 256 blocks
    int p = idx >> 5, k4 = idx & 31;
    float4 v = z4[(size_t)g_perm[p] * 32 + k4];
    split4(v, (__nv_bfloat162*)g_zg_h, (__nv_bfloat162*)g_zg_l, idx);
}

// ---------------------------------------------------------------------------
// GEMM1 tile: bf16 3-term (z @ W1), relu, fp16 output (perm-order rows)
// ---------------------------------------------------------------------------
__device__ void moe_gemm_tile1(const float* __restrict__ bias, int nblk, int tile,
                               char* smem) {
    const int K = Z_, NTOT = H_;
    const int e      = g_tile_e[tile];
    const int row0   = g_tile_r[tile];
    const int off    = g_offsets[e];
    const int cnt    = g_offsets[e + 1] - off;
    const int mvalid = min(BM, cnt - row0);
    const int n0     = nblk * BN;
    const int arow0  = off + row0;

    const uint32_t sb = smem_u32(smem);
    float* sBias = (float*)(smem + OFF_BIAS);
    const int t = threadIdx.x;
    const int lane = t & 31;
    const int wid = t >> 5;

    if (t < 128) sBias[t] = bias[(size_t)e * NTOT + n0 + t];

    const __nv_bfloat16* BhE = g_w1_h + (size_t)e * NTOT * K;
    const __nv_bfloat16* BlE = g_w1_l + (size_t)e * NTOT * K;
    const int NS = K / BK;

    auto load_stage = [&](int s) {
        const int k0 = s * BK;
        const uint32_t base = sb + (s % NSTG) * STAGE;
        #pragma unroll
        for (int i = 0; i < 2; i++) {
            int idx = t + i * 256;
            int r = idx >> 2, kc = idx & 3;
            uint32_t d = (uint32_t)(r * 80 + kc * 16);
            size_t so = (size_t)(arow0 + r) * K + k0 + kc * 8;
            cp16(base + OFF_AH + d, g_zg_h + so);
            cp16(base + OFF_AL + d, g_zg_l + so);
        }
        #pragma unroll
        for (int i = 0; i < 2; i++) {
            int idx = t + i * 256;
            int kr = idx >> 4, nc = idx & 15;
            uint32_t d = (uint32_t)(kr * 256 + nc * 16) ^ (uint32_t)((kr & 15) << 4);
            size_t so = (size_t)(k0 + kr) * NTOT + n0 + nc * 8;
            cp16(base + OFF_BH + d, BhE + so);
            cp16(base + OFF_BL + d, BlE + so);
        }
        cp_commit();
    };

    const int wm0 = (wid & 3) * 32;
    const int wn0 = (wid >> 2) * 64;

    float acc[2][8][4];
    #pragma unroll
    for (int a = 0; a < 2; a++)
        #pragma unroll
        for (int b = 0; b < 8; b++)
            #pragma unroll
            for (int c = 0; c < 4; c++) acc[a][b][c] = 0.0f;

    load_stage(0);
    load_stage(1);
    load_stage(2);

    for (int s = 0; s < NS; s++) {
        cp_wait2();
        __syncthreads();
        const uint32_t base = sb + (s % NSTG) * STAGE;
        #pragma unroll
        for (int kk = 0; kk < 2; kk++) {
            uint32_t a_h[2][4], a_l[2][4];
            #pragma unroll
            for (int mi = 0; mi < 2; mi++) {
                uint32_t ad = base + OFF_AH +
                    (uint32_t)((wm0 + mi * 16 + (lane & 15)) * 80 + (lane >> 4) * 16 + kk * 32);
                ldsm4(a_h[mi], ad);
                ldsm4(a_l[mi], ad + (OFF_AL - OFF_AH));
            }
            #pragma unroll
            for (int pp = 0; pp < 2; pp++) {
                uint32_t b_h[2][4], b_l[2][4];
                #pragma unroll
                for (int q = 0; q < 2; q++) {
                    int p = pp * 2 + q;
                    uint32_t nb = (uint32_t)((wn0 + p * 16 + (lane >> 4) * 8) * 2);
                    uint32_t bd = base + OFF_BH +
                        (((uint32_t)((kk * 16 + (lane & 15)) * 256) + nb) ^ (uint32_t)((lane & 15) << 4));
                    ldsm4t(b_h[q], bd);
                    ldsm4t(b_l[q], bd + (OFF_BL - OFF_BH));
                }
                #pragma unroll
                for (int mi = 0; mi < 2; mi++)
                    #pragma unroll
                    for (int nq = 0; nq < 4; nq++) {
                        int ni = pp * 4 + nq;
                        int q = nq >> 1, hh = (nq & 1) * 2;
                        mma_bf16(acc[mi][ni], a_h[mi], b_h[q][hh], b_h[q][hh + 1]);
                        mma_bf16(acc[mi][ni], a_h[mi], b_l[q][hh], b_l[q][hh + 1]);
                        mma_bf16(acc[mi][ni], a_l[mi], b_h[q][hh], b_h[q][hh + 1]);
                    }
            }
        }
        __syncthreads();
        if (s + 3 < NS) load_stage(s + 3);
        else cp_commit();
    }

    #pragma unroll
    for (int mi = 0; mi < 2; mi++) {
        #pragma unroll
        for (int half = 0; half < 2; half++) {
            int r = wm0 + mi * 16 + (lane >> 2) + half * 8;
            if (r >= mvalid) continue;
            #pragma unroll
            for (int ni = 0; ni < 8; ni++) {
                int cl = wn0 + ni * 8 + (lane & 3) * 2;
                float v0 = fmaxf(acc[mi][ni][half * 2]     + sBias[cl], 0.0f);
                float v1 = fmaxf(acc[mi][ni][half * 2 + 1] + sBias[cl + 1], 0.0f);
                size_t p = (size_t)(arow0 + r) * NTOT + n0 + cl;
                *(__half2*)(g_hg + p) =
                    __halves2half2(__float2half_rn(v0), __float2half_rn(v1));
            }
        }
    }
}

// ---------------------------------------------------------------------------
// GEMM2 tile: fp16 single-term, BM=128 x BN2=64, 8 warps as 4(M) x 2(N).
// Warp tile 32x32. 3 CTAs/SM target. fp32 scatter epilogue.
// B smem rows are 128B with XOR-((k&7)<<4) swizzle.
// ---------------------------------------------------------------------------
__device__ void moe_gemm_tile2(const float* __restrict__ bias, float* __restrict__ outf,
                               int nblk, int tile, char* smem) {
    const int K = H_, NTOT = O_;
    const int e      = g_tile_e[tile];
    const int row0   = g_tile_r[tile];
    const int off    = g_offsets[e];
    const int cnt    = g_offsets[e + 1] - off;
    const int mvalid = min(BM, cnt - row0);
    const int n0     = nblk * BN2;
    const int arow0  = off + row0;

    const uint32_t sb = smem_u32(smem);
    float* sBias = (float*)(smem + F2_BIAS);
    int*   sPerm = (int*)(smem + F2_PERM);

    const int t = threadIdx.x;
    const int lane = t & 31;
    const int wid = t >> 5;

    if (t < 64) sBias[t] = bias[(size_t)e * NTOT + n0 + t];
    if (t < 128) sPerm[t] = (t < mvalid) ? g_perm[arow0 + t] : 0;

    const __half* BE = g_w2f + (size_t)e * NTOT * K;
    const int NS = K / BK;

    auto load_stage = [&](int s) {
        const int k0 = s * BK;
        const uint32_t base = sb + (s % NSTG) * F2_STAGE;
        #pragma unroll
        for (int i = 0; i < 2; i++) {               // A: 512 chunks of 16B
            int idx = t + i * 256;
            int r = idx >> 2, kc = idx & 3;
            uint32_t d = (uint32_t)(r * 80 + kc * 16);
            cp16(base + F2_A + d, g_hg + (size_t)(arow0 + r) * K + k0 + kc * 8);
        }
        {                                            // B: 256 chunks of 16B
            int kr = t >> 3, nc = t & 7;            // kr 0..31, nc 0..7
            uint32_t d = (uint32_t)(kr * 128 + nc * 16) ^ (uint32_t)((kr & 7) << 4);
            cp16(base + F2_B + d, BE + (size_t)(k0 + kr) * NTOT + n0 + nc * 8);
        }
        cp_commit();
    };

    const int wm0 = (wid & 3) * 32;   // 4 warps along M
    const int wn0 = (wid >> 2) * 32;  // 2 warps along N

    float acc[2][4][4];
    #pragma unroll
    for (int a = 0; a < 2; a++)
        #pragma unroll
        for (int b = 0; b < 4; b++)
            #pragma unroll
            for (int c = 0; c < 4; c++) acc[a][b][c] = 0.0f;

    load_stage(0);
    load_stage(1);
    load_stage(2);

    for (int s = 0; s < NS; s++) {
        cp_wait2();
        __syncthreads();
        const uint32_t base = sb + (s % NSTG) * F2_STAGE;
        #pragma unroll
        for (int kk = 0; kk < 2; kk++) {
            uint32_t a[2][4];
            #pragma unroll
            for (int mi = 0; mi < 2; mi++) {
                uint32_t ad = base + F2_A +
                    (uint32_t)((wm0 + mi * 16 + (lane & 15)) * 80 + (lane >> 4) * 16 + kk * 32);
                ldsm4(a[mi], ad);
            }
            uint32_t b[2][4];
            #pragma unroll
            for (int q = 0; q < 2; q++) {
                uint32_t nb = (uint32_t)((wn0 + q * 16 + (lane >> 4) * 8) * 2);
                uint32_t bd = base + F2_B +
                    (((uint32_t)((kk * 16 + (lane & 15)) * 128) + nb) ^ (uint32_t)((lane & 7) << 4));
                ldsm4t(b[q], bd);
            }
            #pragma unroll
            for (int mi = 0; mi < 2; mi++)
                #pragma unroll
                for (int ni = 0; ni < 4; ni++) {
                    int q = ni >> 1, hh = (ni & 1) * 2;
                    mma_f16(acc[mi][ni], a[mi], b[q][hh], b[q][hh + 1]);
                }
        }
        __syncthreads();
        if (s + 3 < NS) load_stage(s + 3);
        else cp_commit();
    }

    #pragma unroll
    for (int mi = 0; mi < 2; mi++) {
        #pragma unroll
        for (int half = 0; half < 2; half++) {
            int r = wm0 + mi * 16 + (lane >> 2) + half * 8;
            if (r >= mvalid) continue;
            #pragma unroll
            for (int ni = 0; ni < 4; ni++) {
                int cl = wn0 + ni * 8 + (lane & 3) * 2;
                float v0 = acc[mi][ni][half * 2]     + sBias[cl];
                float v1 = acc[mi][ni][half * 2 + 1] + sBias[cl + 1];
                size_t p = (size_t)sPerm[r] * NTOT + n0 + cl;
                *(float2*)(outf + p) = make_float2(v0, v1);
            }
        }
    }
}

// ---------------------------------------------------------------------------
__global__ __launch_bounds__(256, 2)
void moe_mma1(const float* __restrict__ b1) {
    extern __shared__ char smem[];
    int tile = blockIdx.x >> 3;
    if (tile >= g_num_tiles) return;
    moe_gemm_tile1(b1, blockIdx.x & 7, tile, smem);
}

__global__ __launch_bounds__(256, 3)
void moe_mma2(const float* __restrict__ b2, float* __restrict__ out) {
    extern __shared__ char smem[];
    int tile = blockIdx.y;
    if (tile >= g_num_tiles) return;
    moe_gemm_tile2(b2, out, blockIdx.x, tile, smem);
}

// ---------------------------------------------------------------------------
extern "C" void kernel_launch(void* const* d_in, const int* in_sizes, int n_in,
                              void* d_out, int out_size) {
    const float* z  = (const float*)d_in[0];
    const float* W1 = (const float*)d_in[1];
    const float* b1 = (const float*)d_in[2];
    const float* W2 = (const float*)d_in[3];
    const float* b2 = (const float*)d_in[4];
    float* out = (float*)d_out;

    static cudaStream_t s_side = nullptr;
    static cudaEvent_t ev_fork = nullptr, ev_join = nullptr;
    if (!s_side) {
        cudaStreamCreateWithFlags(&s_side, cudaStreamNonBlocking);
        cudaEventCreateWithFlags(&ev_fork, cudaEventDisableTiming);
        cudaEventCreateWithFlags(&ev_join, cudaEventDisableTiming);
        cudaFuncSetAttribute(moe_mma1, cudaFuncAttributeMaxDynamicSharedMemorySize, SMEM_TOTAL);
        cudaFuncSetAttribute(moe_mma2, cudaFuncAttributeMaxDynamicSharedMemorySize, SMEM2_TOTAL);
    }

    // Fork: W2 convert (routing-independent) overlaps the routing chain + GEMM1.
    cudaEventRecord(ev_fork, 0);
    cudaStreamWaitEvent(s_side, ev_fork, 0);
    w2conv<<<CONVB, 256, 0, s_side>>>((const float4*)W2);

    route_w1<<<8 + W1_BLOCKS, 256>>>(z, (const float4*)W1);
    scan_scatter<<<1, 1024>>>();
    prep_z<<<256, 256>>>((const float4*)z);
    moe_mma1<<<G1_BLOCKS, 256, SMEM_TOTAL>>>(b1);

    // Join: GEMM2 needs both g_hg (main) and g_w2f (side).
    cudaEventRecord(ev_join, s_side);
    cudaStreamWaitEvent(0, ev_join, 0);
    moe_mma2<<<dim3(O_ / BN2, MAXT), 256, SMEM2_TOTAL>>>(b2, out);
}

// round 14
// speedup vs baseline: 1.0258x; 1.0258x over previous
#include <cuda_runtime.h>
#include <cuda_bf16.h>
#include <cuda_fp16.h>
#include <cstdint>

// ---------------------------------------------------------------------------
constexpr int B_ = 2048, Z_ = 128, H_ = 1024, O_ = 3072, E_ = 8;
constexpr int MAXT = B_ / 128 + E_;   // 24
constexpr int BM = 128, BN = 128, BK = 32;
constexpr int NSTG = 3;

// GEMM1 (bf16 3-term) stage layout: A hi/lo 128x32 (80B-stride), B hi/lo 32x128
constexpr int OFF_AH = 0;
constexpr int OFF_AL = 10240;
constexpr int OFF_BH = 20480;
constexpr int OFF_BL = 28672;
constexpr int STAGE  = 36864;
constexpr int OFF_BIAS = NSTG * STAGE;       // 110592
constexpr int OFF_PERM = OFF_BIAS + 512;
constexpr int SMEM_TOTAL = OFF_PERM + 512;   // 111616

// GEMM2 (fp16 single-term, BN=128): A 128x32 fp16 (80B rows), B 32x128 fp16
// 4-stage ring, single barrier per stage.
constexpr int NSTG2 = 4;
constexpr int F2_A  = 0;
constexpr int F2_B  = 10240;
constexpr int F2_STAGE = 18432;
constexpr int F2_BIAS = NSTG2 * F2_STAGE;    // 73728 (128 floats)
constexpr int F2_PERM = F2_BIAS + 512;
constexpr int SMEM2_TOTAL = F2_PERM + 512;   // 74752

constexpr int G1_BLOCKS = (H_ / BN) * MAXT;  // 192
constexpr int CONVB    = 2048;               // W2 convert blocks
constexpr int W1_BLOCKS = E_ * Z_ * H_ / 4 / 256;   // 1024

// ---------------------------------------------------------------------------
__device__ int g_idx[B_], g_offsets[E_ + 1], g_perm[B_];
__device__ int g_tile_e[MAXT], g_tile_r[MAXT], g_num_tiles;

__device__ __align__(16) __nv_bfloat16 g_zg_h[(B_ + 128) * Z_];
__device__ __align__(16) __nv_bfloat16 g_zg_l[(B_ + 128) * Z_];
__device__ __align__(16) __half       g_hg[(B_ + 128) * H_];
__device__ __align__(16) __nv_bfloat16 g_w1_h[E_ * Z_ * H_];
__device__ __align__(16) __nv_bfloat16 g_w1_l[E_ * Z_ * H_];
__device__ __align__(16) __half       g_w2f[(size_t)E_ * H_ * O_];

// ---------------------------------------------------------------------------
// PTX helpers (arch-agnostic, sm_80+)
// ---------------------------------------------------------------------------
__device__ __forceinline__ uint32_t smem_u32(const void* p) {
    return (uint32_t)__cvta_generic_to_shared(p);
}
__device__ __forceinline__ void cp16(uint32_t dst, const void* src) {
    asm volatile("cp.async.cg.shared.global [%0], [%1], 16;" :: "r"(dst), "l"(src) : "memory");
}
__device__ __forceinline__ void cp_commit() {
    asm volatile("cp.async.commit_group;" ::: "memory");
}
__device__ __forceinline__ void cp_wait2() {
    asm volatile("cp.async.wait_group 2;" ::: "memory");
}
__device__ __forceinline__ void ldsm4(uint32_t* r, uint32_t a) {
    asm volatile("ldmatrix.sync.aligned.m8n8.x4.shared.b16 {%0,%1,%2,%3}, [%4];"
                 : "=r"(r[0]), "=r"(r[1]), "=r"(r[2]), "=r"(r[3]) : "r"(a));
}
__device__ __forceinline__ void ldsm4t(uint32_t* r, uint32_t a) {
    asm volatile("ldmatrix.sync.aligned.m8n8.x4.trans.shared.b16 {%0,%1,%2,%3}, [%4];"
                 : "=r"(r[0]), "=r"(r[1]), "=r"(r[2]), "=r"(r[3]) : "r"(a));
}
__device__ __forceinline__ void mma_bf16(float* d, const uint32_t* a, uint32_t b0, uint32_t b1) {
    asm volatile(
        "mma.sync.aligned.m16n8k16.row.col.f32.bf16.bf16.f32 "
        "{%0,%1,%2,%3}, {%4,%5,%6,%7}, {%8,%9}, {%0,%1,%2,%3};"
        : "+f"(d[0]), "+f"(d[1]), "+f"(d[2]), "+f"(d[3])
        : "r"(a[0]), "r"(a[1]), "r"(a[2]), "r"(a[3]), "r"(b0), "r"(b1));
}
__device__ __forceinline__ void mma_f16(float* d, const uint32_t* a, uint32_t b0, uint32_t b1) {
    asm volatile(
        "mma.sync.aligned.m16n8k16.row.col.f32.f16.f16.f32 "
        "{%0,%1,%2,%3}, {%4,%5,%6,%7}, {%8,%9}, {%0,%1,%2,%3};"
        : "+f"(d[0]), "+f"(d[1]), "+f"(d[2]), "+f"(d[3])
        : "r"(a[0]), "r"(a[1]), "r"(a[2]), "r"(a[3]), "r"(b0), "r"(b1));
}

__device__ __forceinline__ void split4(float4 v, __nv_bfloat162* dh,
                                       __nv_bfloat162* dl, int i) {
    __nv_bfloat16 h0 = __float2bfloat16(v.x), h1 = __float2bfloat16(v.y);
    __nv_bfloat16 h2 = __float2bfloat16(v.z), h3 = __float2bfloat16(v.w);
    __nv_bfloat16 l0 = __float2bfloat16(v.x - __bfloat162float(h0));
    __nv_bfloat16 l1 = __float2bfloat16(v.y - __bfloat162float(h1));
    __nv_bfloat16 l2 = __float2bfloat16(v.z - __bfloat162float(h2));
    __nv_bfloat16 l3 = __float2bfloat16(v.w - __bfloat162float(h3));
    dh[2 * i]     = __nv_bfloat162(h0, h1);
    dh[2 * i + 1] = __nv_bfloat162(h2, h3);
    dl[2 * i]     = __nv_bfloat162(l0, l1);
    dl[2 * i + 1] = __nv_bfloat162(l2, l3);
}

__device__ __forceinline__ void cvt_f16_store8(__half2* dst, int i, float4 v) {
    __half2 a = __halves2half2(__float2half_rn(v.x), __float2half_rn(v.y));
    __half2 b = __halves2half2(__float2half_rn(v.z), __float2half_rn(v.w));
    uint2 u;
    u.x = *(uint32_t*)&a;
    u.y = *(uint32_t*)&b;
    *(uint2*)(dst + 2 * i) = u;
}

// ---------------------------------------------------------------------------
// route (blocks 0..7) fused with W1 split (blocks 8..) — main stream.
// Routing is bit-exact vs JAX (exact small integers in fp32).
// ---------------------------------------------------------------------------
__global__ void route_w1(const float* __restrict__ z, const float4* __restrict__ W1) {
    int bid = blockIdx.x, t = threadIdx.x;
    if (bid < 8) {
        int i = bid * 256 + t;
        const float* zr = z + (size_t)i * Z_;
        float s = 0.0f;
        #pragma unroll 8
        for (int k = 0; k < Z_; k++)
            s += floorf(fabsf(zr[k]) * 1000.0f);
        g_idx[i] = ((int)s) & (E_ - 1);
    } else {
        int i = (bid - 8) * 256 + t;   // < 262144
        split4(W1[i], (__nv_bfloat162*)g_w1_h, (__nv_bfloat162*)g_w1_l, i);
    }
}

// W2 fp32 -> fp16 convert; side stream, full occupancy.
__global__ void w2conv(const float4* __restrict__ W2) {
    const int stride = CONVB * 256;
    __half2* dst = (__half2*)g_w2f;
    int base = blockIdx.x * 256 + threadIdx.x;
    #pragma unroll
    for (int o = 0; o < 3; o++) {
        int i0 = base + (o * 4) * stride;
        float4 v0 = W2[i0];
        float4 v1 = W2[i0 + stride];
        float4 v2 = W2[i0 + 2 * stride];
        float4 v3 = W2[i0 + 3 * stride];
        cvt_f16_store8(dst, i0,              v0);
        cvt_f16_store8(dst, i0 + stride,     v1);
        cvt_f16_store8(dst, i0 + 2 * stride, v2);
        cvt_f16_store8(dst, i0 + 3 * stride, v3);
    }
}

__global__ void scan_scatter() {
    __shared__ int cnt[E_], cur[E_], offs[E_];
    int t = threadIdx.x;
    if (t < E_) { cnt[t] = 0; cur[t] = 0; }
    __syncthreads();
    for (int i = t; i < B_; i += blockDim.x) atomicAdd(&cnt[g_idx[i]], 1);
    __syncthreads();
    if (t == 0) {
        int o = 0, nt = 0;
        g_offsets[0] = 0;
        for (int e = 0; e < E_; e++) {
            int c = cnt[e];
            offs[e] = o;
            for (int r = 0; r < c; r += BM) { g_tile_e[nt] = e; g_tile_r[nt] = r; nt++; }
            o += c;
            g_offsets[e + 1] = o;
        }
        g_num_tiles = nt;
    }
    __syncthreads();
    for (int i = t; i < B_; i += blockDim.x) {
        int e = g_idx[i];
        int pos = offs[e] + atomicAdd(&cur[e], 1);
        g_perm[pos] = i;
    }
}

// z gather + bf16 hi/lo split (perm-dependent)
__global__ void prep_z(const float4* __restrict__ z4) {
    int idx = blockIdx.x * 256 + threadIdx.x;    // 256 blocks
    int p = idx >> 5, k4 = idx & 31;
    float4 v = z4[(size_t)g_perm[p] * 32 + k4];
    split4(v, (__nv_bfloat162*)g_zg_h, (__nv_bfloat162*)g_zg_l, idx);
}

// ---------------------------------------------------------------------------
// GEMM1 tile: bf16 3-term (z @ W1), relu, fp16 output (perm-order rows)
// ---------------------------------------------------------------------------
__device__ void moe_gemm_tile1(const float* __restrict__ bias, int nblk, int tile,
                               char* smem) {
    const int K = Z_, NTOT = H_;
    const int e      = g_tile_e[tile];
    const int row0   = g_tile_r[tile];
    const int off    = g_offsets[e];
    const int cnt    = g_offsets[e + 1] - off;
    const int mvalid = min(BM, cnt - row0);
    const int n0     = nblk * BN;
    const int arow0  = off + row0;

    const uint32_t sb = smem_u32(smem);
    float* sBias = (float*)(smem + OFF_BIAS);
    const int t = threadIdx.x;
    const int lane = t & 31;
    const int wid = t >> 5;

    if (t < 128) sBias[t] = bias[(size_t)e * NTOT + n0 + t];

    const __nv_bfloat16* BhE = g_w1_h + (size_t)e * NTOT * K;
    const __nv_bfloat16* BlE = g_w1_l + (size_t)e * NTOT * K;
    const int NS = K / BK;

    auto load_stage = [&](int s) {
        const int k0 = s * BK;
        const uint32_t base = sb + (s % NSTG) * STAGE;
        #pragma unroll
        for (int i = 0; i < 2; i++) {
            int idx = t + i * 256;
            int r = idx >> 2, kc = idx & 3;
            uint32_t d = (uint32_t)(r * 80 + kc * 16);
            size_t so = (size_t)(arow0 + r) * K + k0 + kc * 8;
            cp16(base + OFF_AH + d, g_zg_h + so);
            cp16(base + OFF_AL + d, g_zg_l + so);
        }
        #pragma unroll
        for (int i = 0; i < 2; i++) {
            int idx = t + i * 256;
            int kr = idx >> 4, nc = idx & 15;
            uint32_t d = (uint32_t)(kr * 256 + nc * 16) ^ (uint32_t)((kr & 15) << 4);
            size_t so = (size_t)(k0 + kr) * NTOT + n0 + nc * 8;
            cp16(base + OFF_BH + d, BhE + so);
            cp16(base + OFF_BL + d, BlE + so);
        }
        cp_commit();
    };

    const int wm0 = (wid & 3) * 32;
    const int wn0 = (wid >> 2) * 64;

    float acc[2][8][4];
    #pragma unroll
    for (int a = 0; a < 2; a++)
        #pragma unroll
        for (int b = 0; b < 8; b++)
            #pragma unroll
            for (int c = 0; c < 4; c++) acc[a][b][c] = 0.0f;

    load_stage(0);
    load_stage(1);
    load_stage(2);

    for (int s = 0; s < NS; s++) {
        cp_wait2();
        __syncthreads();
        const uint32_t base = sb + (s % NSTG) * STAGE;
        #pragma unroll
        for (int kk = 0; kk < 2; kk++) {
            uint32_t a_h[2][4], a_l[2][4];
            #pragma unroll
            for (int mi = 0; mi < 2; mi++) {
                uint32_t ad = base + OFF_AH +
                    (uint32_t)((wm0 + mi * 16 + (lane & 15)) * 80 + (lane >> 4) * 16 + kk * 32);
                ldsm4(a_h[mi], ad);
                ldsm4(a_l[mi], ad + (OFF_AL - OFF_AH));
            }
            #pragma unroll
            for (int pp = 0; pp < 2; pp++) {
                uint32_t b_h[2][4], b_l[2][4];
                #pragma unroll
                for (int q = 0; q < 2; q++) {
                    int p = pp * 2 + q;
                    uint32_t nb = (uint32_t)((wn0 + p * 16 + (lane >> 4) * 8) * 2);
                    uint32_t bd = base + OFF_BH +
                        (((uint32_t)((kk * 16 + (lane & 15)) * 256) + nb) ^ (uint32_t)((lane & 15) << 4));
                    ldsm4t(b_h[q], bd);
                    ldsm4t(b_l[q], bd + (OFF_BL - OFF_BH));
                }
                #pragma unroll
                for (int mi = 0; mi < 2; mi++)
                    #pragma unroll
                    for (int nq = 0; nq < 4; nq++) {
                        int ni = pp * 4 + nq;
                        int q = nq >> 1, hh = (nq & 1) * 2;
                        mma_bf16(acc[mi][ni], a_h[mi], b_h[q][hh], b_h[q][hh + 1]);
                        mma_bf16(acc[mi][ni], a_h[mi], b_l[q][hh], b_l[q][hh + 1]);
                        mma_bf16(acc[mi][ni], a_l[mi], b_h[q][hh], b_h[q][hh + 1]);
                    }
            }
        }
        __syncthreads();
        if (s + 3 < NS) load_stage(s + 3);
        else cp_commit();
    }

    #pragma unroll
    for (int mi = 0; mi < 2; mi++) {
        #pragma unroll
        for (int half = 0; half < 2; half++) {
            int r = wm0 + mi * 16 + (lane >> 2) + half * 8;
            if (r >= mvalid) continue;
            #pragma unroll
            for (int ni = 0; ni < 8; ni++) {
                int cl = wn0 + ni * 8 + (lane & 3) * 2;
                float v0 = fmaxf(acc[mi][ni][half * 2]     + sBias[cl], 0.0f);
                float v1 = fmaxf(acc[mi][ni][half * 2 + 1] + sBias[cl + 1], 0.0f);
                size_t p = (size_t)(arow0 + r) * NTOT + n0 + cl;
                *(__half2*)(g_hg + p) =
                    __halves2half2(__float2half_rn(v0), __float2half_rn(v1));
            }
        }
    }
}

// ---------------------------------------------------------------------------
// GEMM2 tile: fp16 single-term, BM=128 x BN=128, 4-stage ring, ONE barrier
// per stage (load of s+3 never touches the buffer being consumed (s%4), and
// the consumed buffer is only rewritten after the NEXT barrier).
// ---------------------------------------------------------------------------
__device__ void moe_gemm_tile2(const float* __restrict__ bias, float* __restrict__ outf,
                               int nblk, int tile, char* smem) {
    const int K = H_, NTOT = O_;
    const int e      = g_tile_e[tile];
    const int row0   = g_tile_r[tile];
    const int off    = g_offsets[e];
    const int cnt    = g_offsets[e + 1] - off;
    const int mvalid = min(BM, cnt - row0);
    const int n0     = nblk * BN;
    const int arow0  = off + row0;

    const uint32_t sb = smem_u32(smem);
    float* sBias = (float*)(smem + F2_BIAS);
    int*   sPerm = (int*)(smem + F2_PERM);

    const int t = threadIdx.x;
    const int lane = t & 31;
    const int wid = t >> 5;

    if (t < 128) {
        sBias[t] = bias[(size_t)e * NTOT + n0 + t];
        sPerm[t] = (t < mvalid) ? g_perm[arow0 + t] : 0;
    }

    const __half* BE = g_w2f + (size_t)e * NTOT * K;
    const int NS = K / BK;

    auto load_stage = [&](int s) {
        const int k0 = s * BK;
        const uint32_t base = sb + (s % NSTG2) * F2_STAGE;
        #pragma unroll
        for (int i = 0; i < 2; i++) {               // A: 512 chunks of 16B
            int idx = t + i * 256;
            int r = idx >> 2, kc = idx & 3;
            uint32_t d = (uint32_t)(r * 80 + kc * 16);
            cp16(base + F2_A + d, g_hg + (size_t)(arow0 + r) * K + k0 + kc * 8);
        }
        #pragma unroll
        for (int i = 0; i < 2; i++) {               // B: 512 chunks of 16B
            int idx = t + i * 256;
            int kr = idx >> 4, nc = idx & 15;
            uint32_t d = (uint32_t)(kr * 256 + nc * 16) ^ (uint32_t)((kr & 15) << 4);
            cp16(base + F2_B + d, BE + (size_t)(k0 + kr) * NTOT + n0 + nc * 8);
        }
        cp_commit();
    };

    const int wm0 = (wid & 3) * 32;
    const int wn0 = (wid >> 2) * 64;

    float acc[2][8][4];
    #pragma unroll
    for (int a = 0; a < 2; a++)
        #pragma unroll
        for (int b = 0; b < 8; b++)
            #pragma unroll
            for (int c = 0; c < 4; c++) acc[a][b][c] = 0.0f;

    load_stage(0);
    load_stage(1);
    load_stage(2);

    for (int s = 0; s < NS; s++) {
        cp_wait2();
        __syncthreads();
        // Issue next load FIRST: writes buffer (s+3)%4 — disjoint from the
        // consumed buffer s%4; overlaps LSU issue with MMA compute below.
        if (s + 3 < NS) load_stage(s + 3);
        else cp_commit();                            // keep group count aligned

        const uint32_t base = sb + (s % NSTG2) * F2_STAGE;
        #pragma unroll
        for (int kk = 0; kk < 2; kk++) {
            uint32_t a[2][4];
            #pragma unroll
            for (int mi = 0; mi < 2; mi++) {
                uint32_t ad = base + F2_A +
                    (uint32_t)((wm0 + mi * 16 + (lane & 15)) * 80 + (lane >> 4) * 16 + kk * 32);
                ldsm4(a[mi], ad);
            }
            uint32_t b[4][4];
            #pragma unroll
            for (int p = 0; p < 4; p++) {
                uint32_t nb = (uint32_t)((wn0 + p * 16 + (lane >> 4) * 8) * 2);
                uint32_t bd = base + F2_B +
                    (((uint32_t)((kk * 16 + (lane & 15)) * 256) + nb) ^ (uint32_t)((lane & 15) << 4));
                ldsm4t(b[p], bd);
            }
            #pragma unroll
            for (int mi = 0; mi < 2; mi++)
                #pragma unroll
                for (int ni = 0; ni < 8; ni++) {
                    int p = ni >> 1, hh = (ni & 1) * 2;
                    mma_f16(acc[mi][ni], a[mi], b[p][hh], b[p][hh + 1]);
                }
        }
        // NO second barrier: the buffer consumed here (s%4) is next written by
        // load_stage(s+4) at iteration s+1, which is issued only after all
        // warps pass the barrier at the top of iteration s+1.
    }

    #pragma unroll
    for (int mi = 0; mi < 2; mi++) {
        #pragma unroll
        for (int half = 0; half < 2; half++) {
            int r = wm0 + mi * 16 + (lane >> 2) + half * 8;
            if (r >= mvalid) continue;
            #pragma unroll
            for (int ni = 0; ni < 8; ni++) {
                int cl = wn0 + ni * 8 + (lane & 3) * 2;
                float v0 = acc[mi][ni][half * 2]     + sBias[cl];
                float v1 = acc[mi][ni][half * 2 + 1] + sBias[cl + 1];
                size_t p = (size_t)sPerm[r] * NTOT + n0 + cl;
                *(float2*)(outf + p) = make_float2(v0, v1);
            }
        }
    }
}

// ---------------------------------------------------------------------------
__global__ __launch_bounds__(256, 2)
void moe_mma1(const float* __restrict__ b1) {
    extern __shared__ char smem[];
    int tile = blockIdx.x >> 3;
    if (tile >= g_num_tiles) return;
    moe_gemm_tile1(b1, blockIdx.x & 7, tile, smem);
}

__global__ __launch_bounds__(256, 2)
void moe_mma2(const float* __restrict__ b2, float* __restrict__ out) {
    extern __shared__ char smem[];
    int tile = blockIdx.y;
    if (tile >= g_num_tiles) return;
    moe_gemm_tile2(b2, out, blockIdx.x, tile, smem);
}

// ---------------------------------------------------------------------------
extern "C" void kernel_launch(void* const* d_in, const int* in_sizes, int n_in,
                              void* d_out, int out_size) {
    const float* z  = (const float*)d_in[0];
    const float* W1 = (const float*)d_in[1];
    const float* b1 = (const float*)d_in[2];
    const float* W2 = (const float*)d_in[3];
    const float* b2 = (const float*)d_in[4];
    float* out = (float*)d_out;

    static cudaStream_t s_side = nullptr;
    static cudaEvent_t ev_fork = nullptr, ev_join = nullptr;
    if (!s_side) {
        cudaStreamCreateWithFlags(&s_side, cudaStreamNonBlocking);
        cudaEventCreateWithFlags(&ev_fork, cudaEventDisableTiming);
        cudaEventCreateWithFlags(&ev_join, cudaEventDisableTiming);
        cudaFuncSetAttribute(moe_mma1, cudaFuncAttributeMaxDynamicSharedMemorySize, SMEM_TOTAL);
        cudaFuncSetAttribute(moe_mma2, cudaFuncAttributeMaxDynamicSharedMemorySize, SMEM2_TOTAL);
    }

    // Fork: W2 convert (routing-independent) overlaps the routing chain + GEMM1.
    cudaEventRecord(ev_fork, 0);
    cudaStreamWaitEvent(s_side, ev_fork, 0);
    w2conv<<<CONVB, 256, 0, s_side>>>((const float4*)W2);

    route_w1<<<8 + W1_BLOCKS, 256>>>(z, (const float4*)W1);
    scan_scatter<<<1, 1024>>>();
    prep_z<<<256, 256>>>((const float4*)z);
    moe_mma1<<<G1_BLOCKS, 256, SMEM_TOTAL>>>(b1);

    // Join: GEMM2 needs both g_hg (main) and g_w2f (side).
    cudaEventRecord(ev_join, s_side);
    cudaStreamWaitEvent(0, ev_join, 0);
    moe_mma2<<<dim3(O_ / BN, MAXT), 256, SMEM2_TOTAL>>>(b2, out);
}